// round 1
// baseline (speedup 1.0000x reference)
#include <cuda_runtime.h>
#include <cuda_bf16.h>

#define MROWS   131072
#define NDIM    16
#define NBINS   8
#define NELEM   (MROWS * NDIM)          // 2,097,152
#define MIN_BW  0.001f
#define MIN_KS  0.001f

__device__ __forceinline__ float softplus_f(float v) {
    // jax.nn.softplus = log(1 + exp(v)); inputs ~N(0,1) so exp is safe,
    // guard large v anyway for robustness.
    return (v > 15.0f) ? v : __logf(1.0f + __expf(v));
}

__global__ __launch_bounds__(256)
void rqs_coupling_kernel(const float* __restrict__ x_in,
                         const float* __restrict__ w,
                         const float* __restrict__ h,
                         const float* __restrict__ s,
                         const float* __restrict__ shifts,
                         float* __restrict__ out)
{
    int e = blockIdx.x * 256 + threadIdx.x;
    if (e >= NELEM) return;

    const float cdom = 2.0f - (float)NBINS * MIN_BW;   // 1.992

    int row = e >> 4;
    int dim = e & 15;

    float x = x_in[e];
    float ladsum = 0.0f;

    #pragma unroll
    for (int tr = 0; tr < 2; ++tr) {
        size_t base128 = ((size_t)tr * MROWS + (size_t)row) * 128u + (size_t)(dim * 8);
        size_t base112 = ((size_t)tr * MROWS + (size_t)row) * 112u + (size_t)(dim * 7);
        float shift = shifts[(size_t)tr * NELEM + (size_t)e];

        // forward periodic shift: mod(x + shift + 1, 2) - 1 ; arg in [0,3)
        float xs = fmodf(x + shift + 1.0f, 2.0f) - 1.0f;

        // ---- softmax(w), softmax(h): widths / heights ----
        float4 wa = *reinterpret_cast<const float4*>(w + base128);
        float4 wb = *reinterpret_cast<const float4*>(w + base128 + 4);
        float4 ha = *reinterpret_cast<const float4*>(h + base128);
        float4 hb = *reinterpret_cast<const float4*>(h + base128 + 4);

        float ew[8], eh[8];
        ew[0] = __expf(wa.x); ew[1] = __expf(wa.y); ew[2] = __expf(wa.z); ew[3] = __expf(wa.w);
        ew[4] = __expf(wb.x); ew[5] = __expf(wb.y); ew[6] = __expf(wb.z); ew[7] = __expf(wb.w);
        eh[0] = __expf(ha.x); eh[1] = __expf(ha.y); eh[2] = __expf(ha.z); eh[3] = __expf(ha.w);
        eh[4] = __expf(hb.x); eh[5] = __expf(hb.y); eh[6] = __expf(hb.z); eh[7] = __expf(hb.w);

        float sw = ((ew[0] + ew[1]) + (ew[2] + ew[3])) + ((ew[4] + ew[5]) + (ew[6] + ew[7]));
        float sh = ((eh[0] + eh[1]) + (eh[2] + eh[3])) + ((eh[4] + eh[5]) + (eh[6] + eh[7]));

        float cw = __fdividef(cdom, sw);
        float ch = __fdividef(cdom, sh);

        float bw[8], bh[8];
        #pragma unroll
        for (int j = 0; j < 8; ++j) {
            bw[j] = ew[j] * cw + MIN_BW;
            bh[j] = eh[j] * ch + MIN_BW;
        }

        // ---- bin search on cumsum of widths ----
        // idx = count of interior knots <= xs  (in 0..7); x0 = xk[idx]
        float cum = -1.0f;
        float x0  = -1.0f;
        int   idx = 0;
        #pragma unroll
        for (int j = 0; j < 7; ++j) {
            cum += bw[j];
            if (xs >= cum) { idx = j + 1; x0 = cum; }
        }

        // register-select gathers (no local memory)
        float wk = bw[0], hk = bh[0];
        #pragma unroll
        for (int j = 1; j < 8; ++j) {
            if (idx == j) { wk = bw[j]; hk = bh[j]; }
        }
        float y0 = -1.0f;
        #pragma unroll
        for (int j = 0; j < 7; ++j) {
            if (idx > j) y0 += bh[j];
        }

        // ---- knot slopes: only 2 of 7 softplus values are ever used ----
        float d0 = 1.0f, d1 = 1.0f;
        if (idx > 0) d0 = softplus_f(s[base112 + (size_t)(idx - 1)]) + MIN_KS;
        if (idx < 7) d1 = softplus_f(s[base112 + (size_t)idx]) + MIN_KS;

        // ---- rational quadratic spline ----
        float rwk  = __fdividef(1.0f, wk);
        float sk   = hk * rwk;
        float t    = (xs - x0) * rwk;
        float omt  = 1.0f - t;
        float tomt = t * omt;
        float denom = sk + (d1 + d0 - 2.0f * sk) * tomt;
        float rden  = __fdividef(1.0f, denom);
        float y = y0 + hk * (sk * t * t + d0 * tomt) * rden;

        float numer = d1 * t * t + 2.0f * sk * tomt + d0 * omt * omt;
        // ladJ = 2 log sk + log numer - 2 log denom  ==  log(sk^2 * numer * rden^2)
        ladsum += __logf(sk * sk * numer * rden * rden);

        // inverse periodic shift: mod(y - shift + 1, 2) - 1 ; +2 bias keeps arg positive
        x = fmodf(y - shift + 3.0f, 2.0f) - 1.0f;
    }

    out[e]         = x;        // transformed x
    out[NELEM + e] = ladsum;   // log-det-Jacobian sum
}

extern "C" void kernel_launch(void* const* d_in, const int* in_sizes, int n_in,
                              void* d_out, int out_size) {
    const float* x      = (const float*)d_in[0];
    const float* w      = (const float*)d_in[1];
    const float* h      = (const float*)d_in[2];
    const float* s      = (const float*)d_in[3];
    const float* shifts = (const float*)d_in[4];
    float* out = (float*)d_out;

    dim3 block(256);
    dim3 grid((NELEM + 255) / 256);
    rqs_coupling_kernel<<<grid, block>>>(x, w, h, s, shifts, out);
}

// round 2
// speedup vs baseline: 1.1138x; 1.1138x over previous
#include <cuda_runtime.h>
#include <cuda_bf16.h>

#define MROWS   131072
#define NDIM    16
#define NBINS   8
#define NELEM   (MROWS * NDIM)          // 2,097,152
#define MIN_BW  0.001f
#define MIN_KS  0.001f

__device__ __forceinline__ float softplus_f(float v) {
    return (v > 15.0f) ? v : __logf(1.0f + __expf(v));
}

__device__ __forceinline__ float4 ldcs4(const float* p) {
    return __ldcs(reinterpret_cast<const float4*>(p));
}

// One RQS transform (shift -> spline -> unshift). Raw w/h float4s already loaded.
__device__ __forceinline__ float rqs_step(float x, float shift,
                                          float4 wa, float4 wb,
                                          float4 ha, float4 hb,
                                          const float* __restrict__ s_row,
                                          float& ladsum)
{
    const float cdom = 2.0f - (float)NBINS * MIN_BW;   // 1.992

    // forward periodic shift: arg = x + shift + 1 in [0,3); mod 2 then -1
    float arg = x + shift + 1.0f;
    if (arg >= 2.0f) arg -= 2.0f;
    float xs = arg - 1.0f;

    float ew[8], eh[8];
    ew[0] = __expf(wa.x); ew[1] = __expf(wa.y); ew[2] = __expf(wa.z); ew[3] = __expf(wa.w);
    ew[4] = __expf(wb.x); ew[5] = __expf(wb.y); ew[6] = __expf(wb.z); ew[7] = __expf(wb.w);
    eh[0] = __expf(ha.x); eh[1] = __expf(ha.y); eh[2] = __expf(ha.z); eh[3] = __expf(ha.w);
    eh[4] = __expf(hb.x); eh[5] = __expf(hb.y); eh[6] = __expf(hb.z); eh[7] = __expf(hb.w);

    float sw = ((ew[0] + ew[1]) + (ew[2] + ew[3])) + ((ew[4] + ew[5]) + (ew[6] + ew[7]));
    float sh = ((eh[0] + eh[1]) + (eh[2] + eh[3])) + ((eh[4] + eh[5]) + (eh[6] + eh[7]));

    float cw = __fdividef(cdom, sw);
    float ch = __fdividef(cdom, sh);

    float bw[8], bh[8];
    #pragma unroll
    for (int j = 0; j < 8; ++j) {
        bw[j] = ew[j] * cw + MIN_BW;
        bh[j] = eh[j] * ch + MIN_BW;
    }

    // fused bin search + gather: predicated updates as cumsum advances
    float cum = -1.0f + bw[0];
    float x0  = -1.0f;
    float y0  = -1.0f;
    float wk  = bw[0], hk = bh[0];
    int   idx = 0;
    #pragma unroll
    for (int j = 0; j < 7; ++j) {
        if (xs >= cum) {                 // interior knot j+1 <= xs: move to bin j+1
            idx = j + 1;
            x0  = cum;
            y0 += bh[j];
            wk  = bw[j + 1];
            hk  = bh[j + 1];
        }
        if (j < 6) cum += bw[j + 1];
    }

    // knot slopes: only the two flanking this bin are needed
    float d0 = 1.0f, d1 = 1.0f;
    if (idx > 0) d0 = softplus_f(__ldcs(s_row + (idx - 1))) + MIN_KS;
    if (idx < 7) d1 = softplus_f(__ldcs(s_row + idx)) + MIN_KS;

    float rwk  = __fdividef(1.0f, wk);
    float sk   = hk * rwk;
    float t    = (xs - x0) * rwk;
    float omt  = 1.0f - t;
    float tomt = t * omt;
    float denom = sk + (d1 + d0 - 2.0f * sk) * tomt;
    float rden  = __fdividef(1.0f, denom);
    float y = y0 + hk * (sk * t * t + d0 * tomt) * rden;

    float numer = d1 * t * t + 2.0f * sk * tomt + d0 * omt * omt;
    ladsum += __logf(sk * sk * numer * rden * rden);

    // inverse periodic shift: arg2 = y - shift + 3 in [1, 4]; mod 2 then -1
    float arg2 = y - shift + 3.0f;
    if (arg2 >= 2.0f) arg2 -= 2.0f;
    if (arg2 >= 2.0f) arg2 -= 2.0f;
    return arg2 - 1.0f;
}

__global__ __launch_bounds__(256, 4)
void rqs_coupling_kernel(const float* __restrict__ x_in,
                         const float* __restrict__ w,
                         const float* __restrict__ h,
                         const float* __restrict__ s,
                         const float* __restrict__ shifts,
                         float* __restrict__ out)
{
    int e = blockIdx.x * 256 + threadIdx.x;
    if (e >= NELEM) return;

    size_t b0_128 = (size_t)e * 8u;                          // tr0 w/h base
    size_t b1_128 = ((size_t)NELEM + (size_t)e) * 8u;        // tr1 w/h base
    size_t b0_112 = (size_t)e * 7u;                          // tr0 s base
    size_t b1_112 = ((size_t)NELEM + (size_t)e) * 7u;        // tr1 s base

    // ---- front-batched independent loads (11 memory ops in flight) ----
    float  x    = __ldcs(x_in + e);
    float  sh0  = __ldcs(shifts + e);
    float  sh1  = __ldcs(shifts + NELEM + e);
    float4 w0a = ldcs4(w + b0_128);     float4 w0b = ldcs4(w + b0_128 + 4);
    float4 h0a = ldcs4(h + b0_128);     float4 h0b = ldcs4(h + b0_128 + 4);
    float4 w1a = ldcs4(w + b1_128);     float4 w1b = ldcs4(w + b1_128 + 4);
    float4 h1a = ldcs4(h + b1_128);     float4 h1b = ldcs4(h + b1_128 + 4);

    float ladsum = 0.0f;
    x = rqs_step(x, sh0, w0a, w0b, h0a, h0b, s + b0_112, ladsum);
    x = rqs_step(x, sh1, w1a, w1b, h1a, h1b, s + b1_112, ladsum);

    __stcs(out + e, x);
    __stcs(out + NELEM + e, ladsum);
}

extern "C" void kernel_launch(void* const* d_in, const int* in_sizes, int n_in,
                              void* d_out, int out_size) {
    const float* x      = (const float*)d_in[0];
    const float* w      = (const float*)d_in[1];
    const float* h      = (const float*)d_in[2];
    const float* s      = (const float*)d_in[3];
    const float* shifts = (const float*)d_in[4];
    float* out = (float*)d_out;

    rqs_coupling_kernel<<<NELEM / 256, 256>>>(x, w, h, s, shifts, out);
}

// round 3
// speedup vs baseline: 1.1483x; 1.0310x over previous
#include <cuda_runtime.h>
#include <cuda_bf16.h>

#define MROWS   131072
#define NDIM    16
#define NBINS   8
#define NELEM   (MROWS * NDIM)          // 2,097,152
#define MIN_BW  0.001f
#define MIN_KS  0.001f

__device__ __forceinline__ float softplus_f(float v) {
    return (v > 15.0f) ? v : __logf(1.0f + __expf(v));
}

__device__ __forceinline__ float4 ldcs4(const float* p) {
    return __ldcs(reinterpret_cast<const float4*>(p));
}

// One RQS transform (shift -> spline -> unshift). w/h raw float4s in regs,
// slopes staged in shared memory (srow = this thread's 7-float slope row).
__device__ __forceinline__ float rqs_step(float x, float shift,
                                          float4 wa, float4 wb,
                                          float4 ha, float4 hb,
                                          const float* srow,
                                          float& ladsum)
{
    const float cdom = 2.0f - (float)NBINS * MIN_BW;   // 1.992

    // forward periodic shift: arg = x + shift + 1 in [0,3); mod 2 then -1
    float arg = x + shift + 1.0f;
    if (arg >= 2.0f) arg -= 2.0f;
    float xs = arg - 1.0f;

    float ew[8], eh[8];
    ew[0] = __expf(wa.x); ew[1] = __expf(wa.y); ew[2] = __expf(wa.z); ew[3] = __expf(wa.w);
    ew[4] = __expf(wb.x); ew[5] = __expf(wb.y); ew[6] = __expf(wb.z); ew[7] = __expf(wb.w);
    eh[0] = __expf(ha.x); eh[1] = __expf(ha.y); eh[2] = __expf(ha.z); eh[3] = __expf(ha.w);
    eh[4] = __expf(hb.x); eh[5] = __expf(hb.y); eh[6] = __expf(hb.z); eh[7] = __expf(hb.w);

    float sw = ((ew[0] + ew[1]) + (ew[2] + ew[3])) + ((ew[4] + ew[5]) + (ew[6] + ew[7]));
    float sh = ((eh[0] + eh[1]) + (eh[2] + eh[3])) + ((eh[4] + eh[5]) + (eh[6] + eh[7]));

    float cw = __fdividef(cdom, sw);
    float ch = __fdividef(cdom, sh);

    float bw[8], bh[8];
    #pragma unroll
    for (int j = 0; j < 8; ++j) {
        bw[j] = ew[j] * cw + MIN_BW;
        bh[j] = eh[j] * ch + MIN_BW;
    }

    // fused bin search + gather (predicated register selects)
    float cum = -1.0f + bw[0];
    float x0  = -1.0f;
    float y0  = -1.0f;
    float wk  = bw[0], hk = bh[0];
    int   idx = 0;
    #pragma unroll
    for (int j = 0; j < 7; ++j) {
        if (xs >= cum) {
            idx = j + 1;
            x0  = cum;
            y0 += bh[j];
            wk  = bw[j + 1];
            hk  = bh[j + 1];
        }
        if (j < 6) cum += bw[j + 1];
    }

    // flanking knot slopes from shared memory (clamped addresses, predicated value)
    int a0 = (idx > 0) ? idx - 1 : 0;
    int a1 = (idx < 7) ? idx : 6;
    float v0 = srow[a0];
    float v1 = srow[a1];
    float d0 = (idx > 0) ? softplus_f(v0) + MIN_KS : 1.0f;
    float d1 = (idx < 7) ? softplus_f(v1) + MIN_KS : 1.0f;

    float rwk  = __fdividef(1.0f, wk);
    float sk   = hk * rwk;
    float t    = (xs - x0) * rwk;
    float omt  = 1.0f - t;
    float tomt = t * omt;
    float denom = sk + (d1 + d0 - 2.0f * sk) * tomt;
    float rden  = __fdividef(1.0f, denom);
    float y = y0 + hk * (sk * t * t + d0 * tomt) * rden;

    float numer = d1 * t * t + 2.0f * sk * tomt + d0 * omt * omt;
    ladsum += __logf(sk * sk * numer * rden * rden);

    // inverse periodic shift: arg2 = y - shift + 3 in [1, 4]
    float arg2 = y - shift + 3.0f;
    if (arg2 >= 2.0f) arg2 -= 2.0f;
    if (arg2 >= 2.0f) arg2 -= 2.0f;
    return arg2 - 1.0f;
}

__global__ __launch_bounds__(256)
void rqs_coupling_kernel(const float* __restrict__ x_in,
                         const float* __restrict__ w,
                         const float* __restrict__ h,
                         const float* __restrict__ s,
                         const float* __restrict__ shifts,
                         float* __restrict__ out)
{
    // s slope staging: [transform][warp][224 floats] — warp-private regions
    __shared__ __align__(16) float s_stage[2][8][224];

    int e    = blockIdx.x * 256 + threadIdx.x;
    int lane = threadIdx.x & 31;
    int warp = threadIdx.x >> 5;

    size_t b0_128 = (size_t)e * 8u;
    size_t b1_128 = ((size_t)NELEM + (size_t)e) * 8u;

    // warp's contiguous s region (float index), per transform
    size_t sbase0 = (size_t)(blockIdx.x * 256 + warp * 32) * 7u;
    size_t sbase1 = sbase0 + (size_t)NELEM * 7u;

    // ---- front-batched, fully independent, fully coalesced loads ----
    float  x   = __ldcs(x_in + e);
    float  sh0 = __ldcs(shifts + e);
    float  sh1 = __ldcs(shifts + NELEM + e);
    float4 w0a = ldcs4(w + b0_128);     float4 w0b = ldcs4(w + b0_128 + 4);
    float4 h0a = ldcs4(h + b0_128);     float4 h0b = ldcs4(h + b0_128 + 4);
    float4 w1a = ldcs4(w + b1_128);     float4 w1b = ldcs4(w + b1_128 + 4);
    float4 h1a = ldcs4(h + b1_128);     float4 h1b = ldcs4(h + b1_128 + 4);

    // cooperative s loads: 224 floats per warp per transform, 128B/instruction
    float4 sv00 = ldcs4(s + sbase0 + 4 * lane);
    float4 sv10 = ldcs4(s + sbase1 + 4 * lane);
    float4 sv01 = make_float4(0.f, 0.f, 0.f, 0.f);
    float4 sv11 = make_float4(0.f, 0.f, 0.f, 0.f);
    if (lane < 24) {
        sv01 = ldcs4(s + sbase0 + 128 + 4 * lane);
        sv11 = ldcs4(s + sbase1 + 128 + 4 * lane);
    }

    // stage s to shared (warp-private -> syncwarp only)
    *reinterpret_cast<float4*>(&s_stage[0][warp][4 * lane]) = sv00;
    *reinterpret_cast<float4*>(&s_stage[1][warp][4 * lane]) = sv10;
    if (lane < 24) {
        *reinterpret_cast<float4*>(&s_stage[0][warp][128 + 4 * lane]) = sv01;
        *reinterpret_cast<float4*>(&s_stage[1][warp][128 + 4 * lane]) = sv11;
    }
    __syncwarp();

    const float* srow0 = &s_stage[0][warp][7 * lane];
    const float* srow1 = &s_stage[1][warp][7 * lane];

    float ladsum = 0.0f;
    x = rqs_step(x, sh0, w0a, w0b, h0a, h0b, srow0, ladsum);
    x = rqs_step(x, sh1, w1a, w1b, h1a, h1b, srow1, ladsum);

    __stcs(out + e, x);
    __stcs(out + NELEM + e, ladsum);
}

extern "C" void kernel_launch(void* const* d_in, const int* in_sizes, int n_in,
                              void* d_out, int out_size) {
    const float* x      = (const float*)d_in[0];
    const float* w      = (const float*)d_in[1];
    const float* h      = (const float*)d_in[2];
    const float* s      = (const float*)d_in[3];
    const float* shifts = (const float*)d_in[4];
    float* out = (float*)d_out;

    rqs_coupling_kernel<<<NELEM / 256, 256>>>(x, w, h, s, shifts, out);
}